// round 11
// baseline (speedup 1.0000x reference)
#include <cuda_runtime.h>

// Grouped shifted conv:
//   t = roll(x, +1, axis=W); tp = zero-pad t by 1 on W
//   y[o*16+k, n, m] = sum_{i<64, j<3} tp[o*64+i, n, m+j] * W[i,k,j]
//   out[c, n, m] = y[c, (n-1)%56, m]   (roll +1 along H)
//
// Grid (28, 2, 2): one CTA per (row PAIR, group o, m-half). 112 CTAs =
// one balanced wave. Block 1024 = 8 subgroups of 128; subgroup s owns 8
// input channels [8s, 8s+8). Both rows' x loads issued up front. W is
// preloaded into registers (float3 x 8) after the first subgroup barrier
// and reused for both rows -> hot loop is A-reads + FFMA only.
// Producers post per-row psums with bar.arrive and exit; subgroup 0
// computes both rows before consuming psums.

#define NTHREADS 1024
#define RSTRIDE  32

__global__ __launch_bounds__(NTHREADS) void shiftconv_kernel(
    const float* __restrict__ x,   // (128, 56, 56)
    const float* __restrict__ W,   // (64, 16, 3)
    float* __restrict__ out)       // (32, 56, 56)
{
    __shared__ float  ts[2][64 * RSTRIDE];  // double-buffered m-window, cols 0..29
    __shared__ float4 Ws4[64 * 16];         // W[i][k][0..2], .w unused
    __shared__ float4 psum[2][7 * 112];     // per-row partials from subgroups 1..7

    const int nb  = blockIdx.x;             // row pair: rows 2nb, 2nb+1
    const int o   = blockIdx.y;             // channel group
    const int mh  = blockIdx.z;             // m half: 0 -> cols [0,28), 1 -> [28,56)
    const int tid = threadIdx.x;
    const int s   = tid >> 7;               // subgroup 0..7
    const int tl  = tid & 127;
    const int ibase = s * 8;                // 8 channels per subgroup

    // ---- Per-thread staging plan (same for both rows) ----
    int il = 0, q = -2;                     // row-within-slice, quad (-2 = idle)
    if (mh == 0) {
        if (tl < 56)       { il = tl / 7;  q = tl - (tl / 7) * 7; }
        else if (tl < 64)  { il = tl - 56; q = -1; }        // edge thread
    } else {
        if (tl < 64)       { il = tl >> 3; q = tl & 7; }
    }

    // ---- Issue BOTH rows' x loads up front ----
    const float* xbase = x + (o * 64 + ibase) * 3136 + nb * 112;  // np0 = 2nb
    float4 v[2];
    float  e[2];
    #pragma unroll
    for (int r = 0; r < 2; r++) {
        const float* xr = xbase + r * 56 + il * 3136;
        if (mh == 0) {
            if (q >= 0)       v[r] = *(const float4*)(xr + q * 4);   // w0 = 4q
            else if (q == -1) e[r] = xr[55];                          // wrap source
        } else {
            if (q >= 0)       v[r] = *(const float4*)(xr + 24 + q * 4);
        }
    }

    // ---- Stage W slice for this subgroup (8 channels x 16 k = 128 entries) ----
    {
        const int eidx = ibase * 16 + tl;    // one entry per thread
        const float* wp = W + eidx * 3;      // row-major (64,16,3)
        Ws4[eidx] = make_float4(wp[0], wp[1], wp[2], 0.0f);
    }

    const int k  = tl / 7;                   // valid for tl < 112
    const int mq = tl - k * 7;
    const int m  = mq * 4;

    // ---- STS row 0 + row 1 staging function inlined per row ----
    float4 acc[2];
    float3 wreg[8];
    bool wloaded = false;

    #pragma unroll
    for (int r = 0; r < 2; r++) {
        float* dbase = &ts[r][0];
        float* d = &dbase[(ibase + il) * RSTRIDE];
        if (mh == 0) {
            if (q >= 0) {
                const int w0 = q * 4;        // local col = w+2
                *(float2*)(d + w0 + 2) = make_float2(v[r].x, v[r].y);
                *(float2*)(d + w0 + 4) = make_float2(v[r].z, v[r].w);
            } else if (q == -1) {
                d[0] = 0.0f;                 // tp[0] pad
                d[1] = e[r];                 // tp[1] = x[55]
            }
        } else {
            // local col c = w-26 for w in [26,55); c29 = 0 pad
            if (q == 0) {
                d[0] = v[r].z; d[1] = v[r].w;                   // w = 26,27
                d[29] = 0.0f;
            } else if (q == 7) {
                d[26] = v[r].x; d[27] = v[r].y; d[28] = v[r].z; // w = 52..54
            } else if (q > 0) {
                const int c0 = q * 4 - 2;                        // even
                *(float2*)(d + c0)     = make_float2(v[r].x, v[r].y);
                *(float2*)(d + c0 + 2) = make_float2(v[r].z, v[r].w);
            }
        }

        // ---- Subgroup-local barrier (4 warps = 128 threads) ----
        asm volatile("bar.sync %0, 128;" :: "r"(1 + s) : "memory");

        // ---- Preload W into registers once (after first barrier) ----
        if (!wloaded) {
            wloaded = true;
            if (tl < 112) {
                #pragma unroll
                for (int ii = 0; ii < 8; ii++) {
                    const float4 w = Ws4[(ibase + ii) * 16 + k];
                    wreg[ii] = make_float3(w.x, w.y, w.z);
                }
            }
        }

        // ---- Compute partial over this subgroup's 8 channels ----
        float a0 = 0.f, a1 = 0.f, a2 = 0.f, a3 = 0.f;
        if (tl < 112) {
            #pragma unroll
            for (int ii = 0; ii < 8; ii++) {
                const float3 w = wreg[ii];
                const float* row = &dbase[(ibase + ii) * RSTRIDE + m];
                const float4 A = *(const float4*)(row);      // taps m..m+3
                const float2 C = *(const float2*)(row + 4);  // taps m+4, m+5
                a0 += A.x * w.x + A.y * w.y + A.z * w.z;
                a1 += A.y * w.x + A.z * w.y + A.w * w.z;
                a2 += A.z * w.x + A.w * w.y + C.x * w.z;
                a3 += A.w * w.x + C.x * w.y + C.y * w.z;
            }
        }
        acc[r] = make_float4(a0, a1, a2, a3);

        if (s > 0) {
            if (tl < 112) psum[r][(s - 1) * 112 + tl] = acc[r];
            asm volatile("bar.arrive %0, %1;" :: "r"(9 + r), "n"(NTHREADS) : "memory");
        }
    }

    if (s > 0) return;                       // producers done

    // ---- Subgroup 0: reduce + store both rows ----
    #pragma unroll
    for (int r = 0; r < 2; r++) {
        asm volatile("bar.sync %0, %1;" :: "r"(9 + r), "n"(NTHREADS) : "memory");
        if (tl < 112) {
            float4 a = acc[r];
            #pragma unroll
            for (int j = 0; j < 7; j++) {
                const float4 p = psum[r][j * 112 + tl];
                a.x += p.x; a.y += p.y; a.z += p.z; a.w += p.w;
            }
            int nout = nb * 2 + r + 1;       // output H-roll
            if (nout >= 56) nout -= 56;
            *reinterpret_cast<float4*>(
                out + (o * 16 + k) * 3136 + nout * 56 + mh * 28 + m) = a;
        }
    }
}

extern "C" void kernel_launch(void* const* d_in, const int* in_sizes, int n_in,
                              void* d_out, int out_size) {
    const float* x = (const float*)d_in[0];   // 128*56*56 = 401408
    const float* W = (const float*)d_in[1];   // 64*16*3   = 3072
    float* out     = (float*)d_out;           // 32*56*56  = 100352

    dim3 grid(28, 2, 2);
    shiftconv_kernel<<<grid, NTHREADS>>>(x, W, out);
}

// round 12
// speedup vs baseline: 1.0257x; 1.0257x over previous
#include <cuda_runtime.h>

// Grouped shifted conv:
//   t = roll(x, +1, axis=W); tp = zero-pad t by 1 on W
//   y[o*16+k, n, m] = sum_{i<64, j<3} tp[o*64+i, n, m+j] * W[i,k,j]
//   out[c, n, m] = y[c, (n-1)%56, m]   (roll +1 along H)
//
// Minimum-phase layout. Grid (56, 2): one CTA per (input row n', group o),
// 112 CTAs = one balanced wave. Block 1024 = 4 subgroups of 256 threads
// (8 warps); subgroup s owns input channels [16s, 16s+16) and the FULL
// 56-column row. Exactly one staging barrier per subgroup, one 16-iter
// loop, one producer arrive / consumer sync, 3-term psum reduce.

#define NTHREADS 1024
#define RSTRIDE  60

__global__ __launch_bounds__(NTHREADS) void shiftconv_kernel(
    const float* __restrict__ x,   // (128, 56, 56)
    const float* __restrict__ W,   // (64, 16, 3)
    float* __restrict__ out)       // (32, 56, 56)
{
    __shared__ float  ts[64 * RSTRIDE];   // tp rows: [i][p], p in 0..57
    __shared__ float4 Ws4[64 * 16];       // W[i][k][0..2], .w unused
    __shared__ float4 psum[3 * 224];      // partials from subgroups 1..3

    const int np  = blockIdx.x;           // input H-row n'
    const int o   = blockIdx.y;           // channel group
    const int tid = threadIdx.x;
    const int s   = tid >> 8;             // subgroup 0..3
    const int tl  = tid & 255;
    const int ibase = s * 16;

    // ---- Stage this subgroup's W slice (16 i x 16 k = 256 entries) ----
    {
        const int eidx = ibase * 16 + tl;  // one entry per thread
        const float* wp = W + eidx * 3;    // row-major (64,16,3)
        Ws4[eidx] = make_float4(wp[0], wp[1], wp[2], 0.0f);
    }

    // ---- Stage this subgroup's 16 x-rows (224 quads over 256 threads) ----
    // Roll folded in: tp[p] = x[p-2] for p in [2,57], tp[1] = x[55], pads 0.
    if (tl < 224) {
        const int il = tl / 14;            // 0..15
        const int q  = tl - il * 14;       // 0..13
        const int i  = ibase + il;
        const int w0 = q * 4;
        const float4 v = *reinterpret_cast<const float4*>(
            x + (o * 64 + i) * 3136 + np * 56 + w0);
        float* d = &ts[i * RSTRIDE];
        if (q < 13) {
            *(float2*)(d + w0 + 2) = make_float2(v.x, v.y);   // col = w+2
            *(float2*)(d + w0 + 4) = make_float2(v.z, v.w);
        } else {
            d[54] = v.x; d[55] = v.y; d[56] = v.z;            // w = 52..54
            d[1]  = v.w;                                      // w = 55 wraps
        }
    } else if (tl < 240) {
        const int i = ibase + (tl - 224);
        ts[i * RSTRIDE + 0]  = 0.0f;                          // tp[0]
        ts[i * RSTRIDE + 57] = 0.0f;                          // tp[57]
    }

    // ---- Subgroup-local barrier (8 warps = 256 threads) ----
    asm volatile("bar.sync %0, 256;" :: "r"(1 + s) : "memory");

    // ---- Compute: 224 threads cover 16 k x 14 quads ----
    const int k  = tl / 14;                // valid for tl < 224
    const int mq = tl - k * 14;
    const int m  = mq * 4;

    float a0 = 0.f, a1 = 0.f, a2 = 0.f, a3 = 0.f;
    if (tl < 224) {
        #pragma unroll
        for (int ii = 0; ii < 16; ii++) {
            const int i = ibase + ii;
            const float4 w = Ws4[i * 16 + k];
            const float* row = &ts[i * RSTRIDE + m];
            const float4 A = *(const float4*)(row);      // taps m..m+3
            const float2 C = *(const float2*)(row + 4);  // taps m+4, m+5
            a0 += A.x * w.x + A.y * w.y + A.z * w.z;
            a1 += A.y * w.x + A.z * w.y + A.w * w.z;
            a2 += A.z * w.x + A.w * w.y + C.x * w.z;
            a3 += A.w * w.x + C.x * w.y + C.y * w.z;
        }
    }

    if (s > 0) {
        if (tl < 224) psum[(s - 1) * 224 + tl] = make_float4(a0, a1, a2, a3);
        asm volatile("bar.arrive 5, %0;" :: "n"(NTHREADS) : "memory");
        return;
    }

    // ---- Subgroup 0: wait, reduce, store ----
    asm volatile("bar.sync 5, %0;" :: "n"(NTHREADS) : "memory");

    if (tl < 224) {
        const float4 p0 = psum[tl];
        const float4 p1 = psum[224 + tl];
        const float4 p2 = psum[448 + tl];
        a0 += p0.x + p1.x + p2.x;
        a1 += p0.y + p1.y + p2.y;
        a2 += p0.z + p1.z + p2.z;
        a3 += p0.w + p1.w + p2.w;

        int nout = np + 1; if (nout >= 56) nout -= 56;    // output H-roll
        *reinterpret_cast<float4*>(
            out + (o * 16 + k) * 3136 + nout * 56 + m) =
            make_float4(a0, a1, a2, a3);
    }
}

extern "C" void kernel_launch(void* const* d_in, const int* in_sizes, int n_in,
                              void* d_out, int out_size) {
    const float* x = (const float*)d_in[0];   // 128*56*56 = 401408
    const float* W = (const float*)d_in[1];   // 64*16*3   = 3072
    float* out     = (float*)d_out;           // 32*56*56  = 100352

    dim3 grid(56, 2);
    shiftconv_kernel<<<grid, NTHREADS>>>(x, W, out);
}